// round 1
// baseline (speedup 1.0000x reference)
#include <cuda_runtime.h>
#include <math.h>

// Problem constants
constexpr int S_LEN = 4096;
constexpr int BATCH = 2;
constexpr int EMB   = 512;   // E and also H*D
constexpr int NH    = 8;
constexpr int DH    = 64;
constexpr int HALF  = 256;   // sliding window half-width (window 512 -> 513 -> half 256)
constexpr int ROWS  = BATCH * S_LEN;  // 8192

// Scratch (allocation-free rule: __device__ globals)
__device__ float g_q[(size_t)ROWS * EMB];
__device__ float g_k[(size_t)ROWS * EMB];
__device__ float g_v[(size_t)ROWS * EMB];
__device__ float g_att[(size_t)ROWS * EMB];

// ---------------------------------------------------------------------------
// SGEMM: C[M,N] = A[M,K] @ B[K,N], row-major. M%128==0, N%128==0, K%16==0.
// 128x128 block tile, BK=16, 256 threads, 8x8 microtile.
// ---------------------------------------------------------------------------
__global__ __launch_bounds__(256) void sgemm_kernel(
    const float* __restrict__ A, const float* __restrict__ B,
    float* __restrict__ C, int M, int N, int K)
{
    constexpr int BM = 128, BN = 128, BK = 16;
    __shared__ float As[BK][BM + 4];
    __shared__ float Bs[BK][BN + 4];

    const int tid = threadIdx.x;
    const int tx = tid & 15;        // 0..15
    const int ty = tid >> 4;        // 0..15
    const int row0 = blockIdx.y * BM;
    const int col0 = blockIdx.x * BN;

    const int arow = tid >> 2;           // 0..63
    const int acol = (tid & 3) * 4;      // 0,4,8,12
    const int brow = tid >> 5;           // 0..7
    const int bcol = (tid & 31) * 4;     // 0..124

    float acc[8][8] = {};

    for (int k0 = 0; k0 < K; k0 += BK) {
        #pragma unroll
        for (int i = 0; i < 2; i++) {
            int r = arow + i * 64;
            float4 v = *(const float4*)&A[(size_t)(row0 + r) * K + k0 + acol];
            As[acol + 0][r] = v.x;
            As[acol + 1][r] = v.y;
            As[acol + 2][r] = v.z;
            As[acol + 3][r] = v.w;
        }
        #pragma unroll
        for (int i = 0; i < 2; i++) {
            int r = brow + i * 8;
            float4 v = *(const float4*)&B[(size_t)(k0 + r) * N + col0 + bcol];
            *(float4*)&Bs[r][bcol] = v;
        }
        __syncthreads();

        #pragma unroll
        for (int kk = 0; kk < BK; kk++) {
            float ra[8], rb[8];
            *(float4*)&ra[0] = *(float4*)&As[kk][ty * 8];
            *(float4*)&ra[4] = *(float4*)&As[kk][ty * 8 + 4];
            *(float4*)&rb[0] = *(float4*)&Bs[kk][tx * 8];
            *(float4*)&rb[4] = *(float4*)&Bs[kk][tx * 8 + 4];
            #pragma unroll
            for (int i = 0; i < 8; i++)
                #pragma unroll
                for (int j = 0; j < 8; j++)
                    acc[i][j] = fmaf(ra[i], rb[j], acc[i][j]);
        }
        __syncthreads();
    }

    #pragma unroll
    for (int i = 0; i < 8; i++) {
        float* crow = &C[(size_t)(row0 + ty * 8 + i) * N + col0 + tx * 8];
        *(float4*)&crow[0] = make_float4(acc[i][0], acc[i][1], acc[i][2], acc[i][3]);
        *(float4*)&crow[4] = make_float4(acc[i][4], acc[i][5], acc[i][6], acc[i][7]);
    }
}

// ---------------------------------------------------------------------------
// Windowed flash attention with bidirectional ALiBi.
// One CTA = (batch b, head h, 64-query tile). Keys processed in 128-chunks.
// Dynamic SMEM layout (floats):
//   sQt [64][68]   Q transposed: [d][q]
//   sKt [64][132]  K transposed: [d][k]
//   sV  [128][68]  V: [k][d]
//   sP  [128][68]  P: [k][q]
//   red [64][17]   row reduction buffer
//   mS, lS, fS [64] softmax stats
// ---------------------------------------------------------------------------
constexpr int QT = 64;
constexpr int KT = 128;
constexpr int SQ_STRIDE = 68;
constexpr int SK_STRIDE = 132;
constexpr int SMEM_FLOATS = 64*68 + 64*132 + 128*68 + 128*68 + 64*17 + 3*64;
constexpr int SMEM_BYTES  = SMEM_FLOATS * 4;  // 125952

__global__ __launch_bounds__(256) void attn_kernel()
{
    extern __shared__ float smem[];
    float* sQt = smem;                       // 64*68
    float* sKt = sQt + 64 * 68;              // 64*132
    float* sV  = sKt + 64 * 132;             // 128*68
    float* sP  = sV  + 128 * 68;             // 128*68
    float* red = sP  + 128 * 68;             // 64*17
    float* mS  = red + 64 * 17;
    float* lS  = mS + 64;
    float* fS  = lS + 64;

    const int tid = threadIdx.x;
    const int tx = tid & 15;
    const int ty = tid >> 4;
    const int t0 = blockIdx.x * QT;
    const int h  = blockIdx.y;
    const int b  = blockIdx.z;
    const float slope = exp2f(-(float)(h + 1));   // ALiBi slope for H=8

    const float* Qb = g_q   + (size_t)b * S_LEN * EMB + h * DH;
    const float* Kb = g_k   + (size_t)b * S_LEN * EMB + h * DH;
    const float* Vb = g_v   + (size_t)b * S_LEN * EMB + h * DH;
    float*       Ob = g_att + (size_t)b * S_LEN * EMB + h * DH;

    // Load Q tile transposed: sQt[d][q]
    for (int idx = tid; idx < QT * 16; idx += 256) {
        int q = idx >> 4;
        int d = (idx & 15) * 4;
        float4 v = *(const float4*)&Qb[(size_t)(t0 + q) * EMB + d];
        sQt[(d + 0) * SQ_STRIDE + q] = v.x;
        sQt[(d + 1) * SQ_STRIDE + q] = v.y;
        sQt[(d + 2) * SQ_STRIDE + q] = v.z;
        sQt[(d + 3) * SQ_STRIDE + q] = v.w;
    }
    if (tid < QT) { mS[tid] = -1e30f; lS[tid] = 0.0f; }

    float o[4][4] = {};

    const int kbeg = max(0, t0 - HALF);
    const int kend = min(S_LEN, t0 + QT + HALF);

    for (int kstart = kbeg; kstart < kend; kstart += KT) {
        // Load K (transposed) and V chunk
        for (int idx = tid; idx < KT * 16; idx += 256) {
            int kk = idx >> 4;
            int d = (idx & 15) * 4;
            int T = kstart + kk;
            float4 kv = make_float4(0.f, 0.f, 0.f, 0.f);
            float4 vv = make_float4(0.f, 0.f, 0.f, 0.f);
            if (T < S_LEN) {
                kv = *(const float4*)&Kb[(size_t)T * EMB + d];
                vv = *(const float4*)&Vb[(size_t)T * EMB + d];
            }
            sKt[(d + 0) * SK_STRIDE + kk] = kv.x;
            sKt[(d + 1) * SK_STRIDE + kk] = kv.y;
            sKt[(d + 2) * SK_STRIDE + kk] = kv.z;
            sKt[(d + 3) * SK_STRIDE + kk] = kv.w;
            *(float4*)&sV[kk * SQ_STRIDE + d] = vv;
        }
        __syncthreads();

        // S = Q @ K^T  (rows ty*4..+3, cols tx*8..+7)
        float s[4][8] = {};
        #pragma unroll 8
        for (int d = 0; d < DH; d++) {
            float ra[4], rb[8];
            *(float4*)&ra[0] = *(float4*)&sQt[d * SQ_STRIDE + ty * 4];
            *(float4*)&rb[0] = *(float4*)&sKt[d * SK_STRIDE + tx * 8];
            *(float4*)&rb[4] = *(float4*)&sKt[d * SK_STRIDE + tx * 8 + 4];
            #pragma unroll
            for (int i = 0; i < 4; i++)
                #pragma unroll
                for (int j = 0; j < 8; j++)
                    s[i][j] = fmaf(ra[i], rb[j], s[i][j]);
        }

        // Scale + ALiBi bias + sliding-window mask; per-row local max
        #pragma unroll
        for (int i = 0; i < 4; i++) {
            int t = t0 + ty * 4 + i;
            float lmax = -1e30f;
            #pragma unroll
            for (int j = 0; j < 8; j++) {
                int T = kstart + tx * 8 + j;
                int dlt = t - T;
                bool valid = (T < S_LEN) && (dlt <= HALF) && (dlt >= -HALF);
                float val = valid ? fmaf(s[i][j], 0.125f, -slope * fabsf((float)dlt))
                                  : -1e30f;
                s[i][j] = val;
                lmax = fmaxf(lmax, val);
            }
            red[(ty * 4 + i) * 17 + tx] = lmax;
        }
        __syncthreads();

        if (tid < QT) {
            float cm = -1e30f;
            #pragma unroll
            for (int j = 0; j < 16; j++) cm = fmaxf(cm, red[tid * 17 + j]);
            float mold = mS[tid];
            float mnew = fmaxf(mold, cm);
            fS[tid] = __expf(mold - mnew);
            mS[tid] = mnew;
        }
        __syncthreads();

        // exp, stage P (k-major), partial row sums, rescale O
        #pragma unroll
        for (int i = 0; i < 4; i++) {
            int r = ty * 4 + i;
            float mrow = mS[r];
            float sum = 0.f;
            #pragma unroll
            for (int j = 0; j < 8; j++) {
                float p = (s[i][j] > -5e29f) ? __expf(s[i][j] - mrow) : 0.f;
                sP[(tx * 8 + j) * SQ_STRIDE + r] = p;
                sum += p;
            }
            red[r * 17 + tx] = sum;
            float f = fS[r];
            #pragma unroll
            for (int j = 0; j < 4; j++) o[i][j] *= f;
        }
        __syncthreads();

        if (tid < QT) {
            float sum = 0.f;
            #pragma unroll
            for (int j = 0; j < 16; j++) sum += red[tid * 17 + j];
            lS[tid] = lS[tid] * fS[tid] + sum;
        }

        // O += P @ V  (rows ty*4..+3, dims tx*4..+3)
        #pragma unroll 8
        for (int kk = 0; kk < KT; kk++) {
            float rp[4], rv[4];
            *(float4*)&rp[0] = *(float4*)&sP[kk * SQ_STRIDE + ty * 4];
            *(float4*)&rv[0] = *(float4*)&sV[kk * SQ_STRIDE + tx * 4];
            #pragma unroll
            for (int i = 0; i < 4; i++)
                #pragma unroll
                for (int j = 0; j < 4; j++)
                    o[i][j] = fmaf(rp[i], rv[j], o[i][j]);
        }
        __syncthreads();
    }

    // Normalize and write
    #pragma unroll
    for (int i = 0; i < 4; i++) {
        int q = ty * 4 + i;
        float li = lS[q];
        float inv = (li > 0.f) ? (1.0f / li) : 0.f;
        float4 v = make_float4(o[i][0] * inv, o[i][1] * inv,
                               o[i][2] * inv, o[i][3] * inv);
        *(float4*)&Ob[(size_t)(t0 + q) * EMB + tx * 4] = v;
    }
}

// ---------------------------------------------------------------------------
extern "C" void kernel_launch(void* const* d_in, const int* in_sizes, int n_in,
                              void* d_out, int out_size)
{
    (void)in_sizes; (void)n_in; (void)out_size;
    const float* inputs_q  = (const float*)d_in[0];
    const float* inputs_kv = (const float*)d_in[1];
    const float* w_q = (const float*)d_in[2];
    const float* w_k = (const float*)d_in[3];
    const float* w_v = (const float*)d_in[4];
    const float* w_o = (const float*)d_in[5];
    float* out = (float*)d_out;

    float *qb, *kb, *vb, *ab;
    cudaGetSymbolAddress((void**)&qb, g_q);
    cudaGetSymbolAddress((void**)&kb, g_k);
    cudaGetSymbolAddress((void**)&vb, g_v);
    cudaGetSymbolAddress((void**)&ab, g_att);

    cudaFuncSetAttribute(attn_kernel,
                         cudaFuncAttributeMaxDynamicSharedMemorySize,
                         SMEM_BYTES);

    dim3 gGemm(EMB / 128, ROWS / 128);   // (4, 64)
    sgemm_kernel<<<gGemm, 256>>>(inputs_q,  w_q, qb, ROWS, EMB, EMB);
    sgemm_kernel<<<gGemm, 256>>>(inputs_kv, w_k, kb, ROWS, EMB, EMB);
    sgemm_kernel<<<gGemm, 256>>>(inputs_kv, w_v, vb, ROWS, EMB, EMB);

    dim3 gAttn(S_LEN / QT, NH, BATCH);   // (64, 8, 2)
    attn_kernel<<<gAttn, 256, SMEM_BYTES>>>();

    sgemm_kernel<<<gGemm, 256>>>(ab, w_o, out, ROWS, EMB, EMB);
}

// round 2
// speedup vs baseline: 1.0982x; 1.0982x over previous
#include <cuda_runtime.h>
#include <math.h>
#include <stdint.h>

// Problem constants
constexpr int S_LEN = 4096;
constexpr int BATCH = 2;
constexpr int EMB   = 512;   // E and also H*D
constexpr int NH    = 8;
constexpr int DH    = 64;
constexpr int HALF  = 256;   // sliding window half-width
constexpr int ROWS  = BATCH * S_LEN;  // 8192

// Scratch (allocation-free rule: __device__ globals)
__device__ float g_q[(size_t)ROWS * EMB];
__device__ float g_k[(size_t)ROWS * EMB];
__device__ float g_v[(size_t)ROWS * EMB];
__device__ float g_att[(size_t)ROWS * EMB];

// ---------------------------------------------------------------------------
// tf32 helpers
// ---------------------------------------------------------------------------
__device__ __forceinline__ uint32_t f2tf32(float x) {
    uint32_t r;
    asm("cvt.rna.tf32.f32 %0, %1;" : "=r"(r) : "f"(x));
    return r;
}

__device__ __forceinline__ void split_tf32(float x, uint32_t& hi, uint32_t& lo) {
    hi = f2tf32(x);
    lo = f2tf32(x - __uint_as_float(hi));
}

__device__ __forceinline__ void mma_tf32(float d[4], const uint32_t a[4],
                                         const uint32_t b[2]) {
    asm volatile(
        "mma.sync.aligned.m16n8k8.row.col.f32.tf32.tf32.f32 "
        "{%0,%1,%2,%3}, {%4,%5,%6,%7}, {%8,%9}, {%0,%1,%2,%3};\n"
        : "+f"(d[0]), "+f"(d[1]), "+f"(d[2]), "+f"(d[3])
        : "r"(a[0]), "r"(a[1]), "r"(a[2]), "r"(a[3]), "r"(b[0]), "r"(b[1]));
}

// ---------------------------------------------------------------------------
// Split-tf32 tensor-core GEMM: C[M,N] = A[M,K] @ B[K,N], row-major.
// CTA tile 128x128, BK=16, 256 threads (8 warps, 2x4 -> 64x32 warp tiles).
// A smem [m][k] stride 20 (frag loads conflict-free: bank=(4m+k)%32 bijective).
// B smem [k][n] stride 132 (frag loads conflict-free: bank=(4k+n)%32 bijective).
// Double-buffered smem stages + register prefetch.
// ---------------------------------------------------------------------------
constexpr int GBM = 128, GBN = 128, GBK = 16;
constexpr int ASTR = 20;    // A smem row stride (words)
constexpr int BSTR = 132;   // B smem row stride (words)
constexpr int A_STAGE = GBM * ASTR;   // 2560 words
constexpr int B_STAGE = GBK * BSTR;   // 2112 words
constexpr int GEMM_SMEM_BYTES = (4 * A_STAGE + 4 * B_STAGE) * 4;  // 74752

__global__ __launch_bounds__(256, 1) void gemm_tf32_kernel(
    const float* __restrict__ A, const float* __restrict__ B,
    float* __restrict__ C, int M, int N, int K)
{
    extern __shared__ uint32_t sm[];
    uint32_t* sAh = sm;                       // [2][A_STAGE]
    uint32_t* sAl = sAh + 2 * A_STAGE;
    uint32_t* sBh = sAl + 2 * A_STAGE;        // [2][B_STAGE]
    uint32_t* sBl = sBh + 2 * B_STAGE;

    const int tid  = threadIdx.x;
    const int lane = tid & 31;
    const int wid  = tid >> 5;
    const int warp_m = wid >> 2;          // 0..1
    const int warp_n = wid & 3;           // 0..3
    const int m_base = warp_m * 64;
    const int n_base = warp_n * 32;
    const int row0 = blockIdx.y * GBM;
    const int col0 = blockIdx.x * GBN;

    // global load mapping
    const int arow = tid >> 2;            // 0..63  (rows arow, arow+64)
    const int acol = (tid & 3) << 2;      // 0,4,8,12
    const int brow = tid >> 5;            // 0..7   (rows brow, brow+8)
    const int bcol = (tid & 31) << 2;     // 0..124

    const float* pA0 = A + (size_t)(row0 + arow) * K + acol;
    const float* pA1 = A + (size_t)(row0 + arow + 64) * K + acol;
    const float* pB0 = B + (size_t)brow * N + col0 + bcol;
    const float* pB1 = B + (size_t)(brow + 8) * N + col0 + bcol;

    const int NT = K / GBK;   // 32 for K=512

    float acc[4][4][4] = {};

    float4 fa0, fa1, fb0, fb1;

    // preload tile 0
    fa0 = *(const float4*)(pA0);
    fa1 = *(const float4*)(pA1);
    fb0 = *(const float4*)(pB0);
    fb1 = *(const float4*)(pB1);

    // store tile 0 to stage 0
    {
        uint32_t h0, l0, h1, l1, h2, l2, h3, l3;
        split_tf32(fa0.x, h0, l0); split_tf32(fa0.y, h1, l1);
        split_tf32(fa0.z, h2, l2); split_tf32(fa0.w, h3, l3);
        *(uint4*)&sAh[arow * ASTR + acol] = make_uint4(h0, h1, h2, h3);
        *(uint4*)&sAl[arow * ASTR + acol] = make_uint4(l0, l1, l2, l3);
        split_tf32(fa1.x, h0, l0); split_tf32(fa1.y, h1, l1);
        split_tf32(fa1.z, h2, l2); split_tf32(fa1.w, h3, l3);
        *(uint4*)&sAh[(arow + 64) * ASTR + acol] = make_uint4(h0, h1, h2, h3);
        *(uint4*)&sAl[(arow + 64) * ASTR + acol] = make_uint4(l0, l1, l2, l3);
        split_tf32(fb0.x, h0, l0); split_tf32(fb0.y, h1, l1);
        split_tf32(fb0.z, h2, l2); split_tf32(fb0.w, h3, l3);
        *(uint4*)&sBh[brow * BSTR + bcol] = make_uint4(h0, h1, h2, h3);
        *(uint4*)&sBl[brow * BSTR + bcol] = make_uint4(l0, l1, l2, l3);
        split_tf32(fb1.x, h0, l0); split_tf32(fb1.y, h1, l1);
        split_tf32(fb1.z, h2, l2); split_tf32(fb1.w, h3, l3);
        *(uint4*)&sBh[(brow + 8) * BSTR + bcol] = make_uint4(h0, h1, h2, h3);
        *(uint4*)&sBl[(brow + 8) * BSTR + bcol] = make_uint4(l0, l1, l2, l3);
    }
    __syncthreads();

    const int qr = lane >> 2;   // 0..7
    const int qc = lane & 3;    // 0..3

    for (int kt = 0; kt < NT; kt++) {
        // prefetch next tile into registers
        if (kt + 1 < NT) {
            int ko = (kt + 1) * GBK;
            fa0 = *(const float4*)(pA0 + ko);
            fa1 = *(const float4*)(pA1 + ko);
            fb0 = *(const float4*)(pB0 + (size_t)ko * N);
            fb1 = *(const float4*)(pB1 + (size_t)ko * N);
        }

        const uint32_t* Ah = sAh + (kt & 1) * A_STAGE;
        const uint32_t* Al = sAl + (kt & 1) * A_STAGE;
        const uint32_t* Bh = sBh + (kt & 1) * B_STAGE;
        const uint32_t* Bl = sBl + (kt & 1) * B_STAGE;

        #pragma unroll
        for (int ks = 0; ks < 2; ks++) {
            const int k0 = ks * 8;
            uint32_t ah[4][4], al[4][4], bh[4][2], bl[4][2];
            #pragma unroll
            for (int mt = 0; mt < 4; mt++) {
                const uint32_t* ph = &Ah[(m_base + mt * 16 + qr) * ASTR + k0 + qc];
                const uint32_t* pl = &Al[(m_base + mt * 16 + qr) * ASTR + k0 + qc];
                ah[mt][0] = ph[0]; ah[mt][1] = ph[8 * ASTR];
                ah[mt][2] = ph[4]; ah[mt][3] = ph[8 * ASTR + 4];
                al[mt][0] = pl[0]; al[mt][1] = pl[8 * ASTR];
                al[mt][2] = pl[4]; al[mt][3] = pl[8 * ASTR + 4];
            }
            #pragma unroll
            for (int nt = 0; nt < 4; nt++) {
                const uint32_t* ph = &Bh[(k0 + qc) * BSTR + n_base + nt * 8 + qr];
                const uint32_t* pl = &Bl[(k0 + qc) * BSTR + n_base + nt * 8 + qr];
                bh[nt][0] = ph[0]; bh[nt][1] = ph[4 * BSTR];
                bl[nt][0] = pl[0]; bl[nt][1] = pl[4 * BSTR];
            }
            #pragma unroll
            for (int mt = 0; mt < 4; mt++)
                #pragma unroll
                for (int nt = 0; nt < 4; nt++) {
                    mma_tf32(acc[mt][nt], ah[mt], bh[nt]);
                    mma_tf32(acc[mt][nt], ah[mt], bl[nt]);
                    mma_tf32(acc[mt][nt], al[mt], bh[nt]);
                }
        }

        // store prefetched tile to the other stage
        if (kt + 1 < NT) {
            uint32_t* dAh = sAh + ((kt + 1) & 1) * A_STAGE;
            uint32_t* dAl = sAl + ((kt + 1) & 1) * A_STAGE;
            uint32_t* dBh = sBh + ((kt + 1) & 1) * B_STAGE;
            uint32_t* dBl = sBl + ((kt + 1) & 1) * B_STAGE;
            uint32_t h0, l0, h1, l1, h2, l2, h3, l3;
            split_tf32(fa0.x, h0, l0); split_tf32(fa0.y, h1, l1);
            split_tf32(fa0.z, h2, l2); split_tf32(fa0.w, h3, l3);
            *(uint4*)&dAh[arow * ASTR + acol] = make_uint4(h0, h1, h2, h3);
            *(uint4*)&dAl[arow * ASTR + acol] = make_uint4(l0, l1, l2, l3);
            split_tf32(fa1.x, h0, l0); split_tf32(fa1.y, h1, l1);
            split_tf32(fa1.z, h2, l2); split_tf32(fa1.w, h3, l3);
            *(uint4*)&dAh[(arow + 64) * ASTR + acol] = make_uint4(h0, h1, h2, h3);
            *(uint4*)&dAl[(arow + 64) * ASTR + acol] = make_uint4(l0, l1, l2, l3);
            split_tf32(fb0.x, h0, l0); split_tf32(fb0.y, h1, l1);
            split_tf32(fb0.z, h2, l2); split_tf32(fb0.w, h3, l3);
            *(uint4*)&dBh[brow * BSTR + bcol] = make_uint4(h0, h1, h2, h3);
            *(uint4*)&dBl[brow * BSTR + bcol] = make_uint4(l0, l1, l2, l3);
            split_tf32(fb1.x, h0, l0); split_tf32(fb1.y, h1, l1);
            split_tf32(fb1.z, h2, l2); split_tf32(fb1.w, h3, l3);
            *(uint4*)&dBh[(brow + 8) * BSTR + bcol] = make_uint4(h0, h1, h2, h3);
            *(uint4*)&dBl[(brow + 8) * BSTR + bcol] = make_uint4(l0, l1, l2, l3);
        }
        __syncthreads();
    }

    // Epilogue: c frag (m16n8): rows qr, qr+8; cols 2*qc, 2*qc+1
    #pragma unroll
    for (int mt = 0; mt < 4; mt++) {
        #pragma unroll
        for (int nt = 0; nt < 4; nt++) {
            int r = row0 + m_base + mt * 16 + qr;
            int c = col0 + n_base + nt * 8 + 2 * qc;
            *(float2*)&C[(size_t)r * N + c] =
                make_float2(acc[mt][nt][0], acc[mt][nt][1]);
            *(float2*)&C[(size_t)(r + 8) * N + c] =
                make_float2(acc[mt][nt][2], acc[mt][nt][3]);
        }
    }
}

// ---------------------------------------------------------------------------
// Windowed flash attention with bidirectional ALiBi (unchanged from R1).
// ---------------------------------------------------------------------------
constexpr int QT = 64;
constexpr int KT = 128;
constexpr int SQ_STRIDE = 68;
constexpr int SK_STRIDE = 132;
constexpr int SMEM_FLOATS = 64*68 + 64*132 + 128*68 + 128*68 + 64*17 + 3*64;
constexpr int SMEM_BYTES  = SMEM_FLOATS * 4;  // 125952

__global__ __launch_bounds__(256) void attn_kernel()
{
    extern __shared__ float smem[];
    float* sQt = smem;                       // 64*68
    float* sKt = sQt + 64 * 68;              // 64*132
    float* sV  = sKt + 64 * 132;             // 128*68
    float* sP  = sV  + 128 * 68;             // 128*68
    float* red = sP  + 128 * 68;             // 64*17
    float* mS  = red + 64 * 17;
    float* lS  = mS + 64;
    float* fS  = lS + 64;

    const int tid = threadIdx.x;
    const int tx = tid & 15;
    const int ty = tid >> 4;
    const int t0 = blockIdx.x * QT;
    const int h  = blockIdx.y;
    const int b  = blockIdx.z;
    const float slope = exp2f(-(float)(h + 1));   // ALiBi slope for H=8

    const float* Qb = g_q   + (size_t)b * S_LEN * EMB + h * DH;
    const float* Kb = g_k   + (size_t)b * S_LEN * EMB + h * DH;
    const float* Vb = g_v   + (size_t)b * S_LEN * EMB + h * DH;
    float*       Ob = g_att + (size_t)b * S_LEN * EMB + h * DH;

    for (int idx = tid; idx < QT * 16; idx += 256) {
        int q = idx >> 4;
        int d = (idx & 15) * 4;
        float4 v = *(const float4*)&Qb[(size_t)(t0 + q) * EMB + d];
        sQt[(d + 0) * SQ_STRIDE + q] = v.x;
        sQt[(d + 1) * SQ_STRIDE + q] = v.y;
        sQt[(d + 2) * SQ_STRIDE + q] = v.z;
        sQt[(d + 3) * SQ_STRIDE + q] = v.w;
    }
    if (tid < QT) { mS[tid] = -1e30f; lS[tid] = 0.0f; }

    float o[4][4] = {};

    const int kbeg = max(0, t0 - HALF);
    const int kend = min(S_LEN, t0 + QT + HALF);

    for (int kstart = kbeg; kstart < kend; kstart += KT) {
        for (int idx = tid; idx < KT * 16; idx += 256) {
            int kk = idx >> 4;
            int d = (idx & 15) * 4;
            int T = kstart + kk;
            float4 kv = make_float4(0.f, 0.f, 0.f, 0.f);
            float4 vv = make_float4(0.f, 0.f, 0.f, 0.f);
            if (T < S_LEN) {
                kv = *(const float4*)&Kb[(size_t)T * EMB + d];
                vv = *(const float4*)&Vb[(size_t)T * EMB + d];
            }
            sKt[(d + 0) * SK_STRIDE + kk] = kv.x;
            sKt[(d + 1) * SK_STRIDE + kk] = kv.y;
            sKt[(d + 2) * SK_STRIDE + kk] = kv.z;
            sKt[(d + 3) * SK_STRIDE + kk] = kv.w;
            *(float4*)&sV[kk * SQ_STRIDE + d] = vv;
        }
        __syncthreads();

        float s[4][8] = {};
        #pragma unroll 8
        for (int d = 0; d < DH; d++) {
            float ra[4], rb[8];
            *(float4*)&ra[0] = *(float4*)&sQt[d * SQ_STRIDE + ty * 4];
            *(float4*)&rb[0] = *(float4*)&sKt[d * SK_STRIDE + tx * 8];
            *(float4*)&rb[4] = *(float4*)&sKt[d * SK_STRIDE + tx * 8 + 4];
            #pragma unroll
            for (int i = 0; i < 4; i++)
                #pragma unroll
                for (int j = 0; j < 8; j++)
                    s[i][j] = fmaf(ra[i], rb[j], s[i][j]);
        }

        #pragma unroll
        for (int i = 0; i < 4; i++) {
            int t = t0 + ty * 4 + i;
            float lmax = -1e30f;
            #pragma unroll
            for (int j = 0; j < 8; j++) {
                int T = kstart + tx * 8 + j;
                int dlt = t - T;
                bool valid = (T < S_LEN) && (dlt <= HALF) && (dlt >= -HALF);
                float val = valid ? fmaf(s[i][j], 0.125f, -slope * fabsf((float)dlt))
                                  : -1e30f;
                s[i][j] = val;
                lmax = fmaxf(lmax, val);
            }
            red[(ty * 4 + i) * 17 + tx] = lmax;
        }
        __syncthreads();

        if (tid < QT) {
            float cm = -1e30f;
            #pragma unroll
            for (int j = 0; j < 16; j++) cm = fmaxf(cm, red[tid * 17 + j]);
            float mold = mS[tid];
            float mnew = fmaxf(mold, cm);
            fS[tid] = __expf(mold - mnew);
            mS[tid] = mnew;
        }
        __syncthreads();

        #pragma unroll
        for (int i = 0; i < 4; i++) {
            int r = ty * 4 + i;
            float mrow = mS[r];
            float sum = 0.f;
            #pragma unroll
            for (int j = 0; j < 8; j++) {
                float p = (s[i][j] > -5e29f) ? __expf(s[i][j] - mrow) : 0.f;
                sP[(tx * 8 + j) * SQ_STRIDE + r] = p;
                sum += p;
            }
            red[r * 17 + tx] = sum;
            float f = fS[r];
            #pragma unroll
            for (int j = 0; j < 4; j++) o[i][j] *= f;
        }
        __syncthreads();

        if (tid < QT) {
            float sum = 0.f;
            #pragma unroll
            for (int j = 0; j < 16; j++) sum += red[tid * 17 + j];
            lS[tid] = lS[tid] * fS[tid] + sum;
        }

        #pragma unroll 8
        for (int kk = 0; kk < KT; kk++) {
            float rp[4], rv[4];
            *(float4*)&rp[0] = *(float4*)&sP[kk * SQ_STRIDE + ty * 4];
            *(float4*)&rv[0] = *(float4*)&sV[kk * SQ_STRIDE + tx * 4];
            #pragma unroll
            for (int i = 0; i < 4; i++)
                #pragma unroll
                for (int j = 0; j < 4; j++)
                    o[i][j] = fmaf(rp[i], rv[j], o[i][j]);
        }
        __syncthreads();
    }

    #pragma unroll
    for (int i = 0; i < 4; i++) {
        int q = ty * 4 + i;
        float li = lS[q];
        float inv = (li > 0.f) ? (1.0f / li) : 0.f;
        float4 v = make_float4(o[i][0] * inv, o[i][1] * inv,
                               o[i][2] * inv, o[i][3] * inv);
        *(float4*)&Ob[(size_t)(t0 + q) * EMB + tx * 4] = v;
    }
}

// ---------------------------------------------------------------------------
extern "C" void kernel_launch(void* const* d_in, const int* in_sizes, int n_in,
                              void* d_out, int out_size)
{
    (void)in_sizes; (void)n_in; (void)out_size;
    const float* inputs_q  = (const float*)d_in[0];
    const float* inputs_kv = (const float*)d_in[1];
    const float* w_q = (const float*)d_in[2];
    const float* w_k = (const float*)d_in[3];
    const float* w_v = (const float*)d_in[4];
    const float* w_o = (const float*)d_in[5];
    float* out = (float*)d_out;

    float *qb, *kb, *vb, *ab;
    cudaGetSymbolAddress((void**)&qb, g_q);
    cudaGetSymbolAddress((void**)&kb, g_k);
    cudaGetSymbolAddress((void**)&vb, g_v);
    cudaGetSymbolAddress((void**)&ab, g_att);

    cudaFuncSetAttribute(attn_kernel,
                         cudaFuncAttributeMaxDynamicSharedMemorySize,
                         SMEM_BYTES);
    cudaFuncSetAttribute(gemm_tf32_kernel,
                         cudaFuncAttributeMaxDynamicSharedMemorySize,
                         GEMM_SMEM_BYTES);

    dim3 gGemm(EMB / GBN, ROWS / GBM);   // (4, 64)
    gemm_tf32_kernel<<<gGemm, 256, GEMM_SMEM_BYTES>>>(inputs_q,  w_q, qb, ROWS, EMB, EMB);
    gemm_tf32_kernel<<<gGemm, 256, GEMM_SMEM_BYTES>>>(inputs_kv, w_k, kb, ROWS, EMB, EMB);
    gemm_tf32_kernel<<<gGemm, 256, GEMM_SMEM_BYTES>>>(inputs_kv, w_v, vb, ROWS, EMB, EMB);

    dim3 gAttn(S_LEN / QT, NH, BATCH);   // (64, 8, 2)
    attn_kernel<<<gAttn, 256, SMEM_BYTES>>>();

    gemm_tf32_kernel<<<gGemm, 256, GEMM_SMEM_BYTES>>>(ab, w_o, out, ROWS, EMB, EMB);
}